// round 1
// baseline (speedup 1.0000x reference)
#include <cuda_runtime.h>

#define HW   256
#define CH   32
#define HID  256
#define PCH  96   // 3 * CH perceive channels

// x2 scratch (allocation-free rule: __device__ global array)
__device__ float g_x2[8 * CH * HW * HW];

// ---------------------------------------------------------------------------
// Kernel 1: perceive (depthwise ident/sobelx/sobely) + per-pixel MLP + fire
//   One CTA per (batch, row). One thread per pixel column.
//   W1 [256,96], W2^T [256,32], b1 staged in dynamic smem (132 KB).
// ---------------------------------------------------------------------------
__global__ __launch_bounds__(256, 1)
void nca_update_kernel(const float* __restrict__ x, const float* __restrict__ ru,
                       const float* __restrict__ W1, const float* __restrict__ b1,
                       const float* __restrict__ W2)
{
    extern __shared__ float smem[];
    float* sW1  = smem;                 // [256][96]
    float* sW2t = smem + HID * PCH;     // [256][32]  (transposed W2)
    float* sb1  = sW2t + HID * CH;      // [256]

    const int tid = threadIdx.x;
    const int b   = blockIdx.x >> 8;
    const int y   = blockIdx.x & 255;

    for (int i = tid; i < HID * PCH; i += 256) sW1[i] = W1[i];
    for (int i = tid; i < CH * HID; i += 256) {
        int o = i >> 8, j = i & 255;        // W2 is [32][256] row-major
        sW2t[j * CH + o] = W2[i];
    }
    sb1[tid] = b1[tid];
    __syncthreads();

    const int xx = tid;
    const float* xb = x + (size_t)b * CH * HW * HW;
    const bool ym = (y > 0), yp = (y < HW - 1);
    const bool xm = (xx > 0), xp = (xx < HW - 1);

    // Perceive: p channel order matches tiled filter bank: [3c]=ident, [3c+1]=gx, [3c+2]=gy
    float p[PCH];
#pragma unroll
    for (int c = 0; c < CH; ++c) {
        const float* xc = xb + c * HW * HW + y * HW + xx;
        float c00 = (ym && xm) ? xc[-HW - 1] : 0.f;
        float c01 =  ym        ? xc[-HW]     : 0.f;
        float c02 = (ym && xp) ? xc[-HW + 1] : 0.f;
        float c10 =  xm        ? xc[-1]      : 0.f;
        float c11 =              xc[0];
        float c12 =  xp        ? xc[1]       : 0.f;
        float c20 = (yp && xm) ? xc[HW - 1]  : 0.f;
        float c21 =  yp        ? xc[HW]      : 0.f;
        float c22 = (yp && xp) ? xc[HW + 1]  : 0.f;
        p[3 * c]     = c11;
        p[3 * c + 1] = ((c02 - c00) + 2.f * (c12 - c10) + (c22 - c20)) * 0.125f;
        p[3 * c + 2] = ((c20 - c00) + 2.f * (c21 - c01) + (c22 - c02)) * 0.125f;
    }

    float upd[CH];
#pragma unroll
    for (int o = 0; o < CH; ++o) upd[o] = 0.f;

    // Stream hidden units; 4-way split accumulators break the FFMA RAW chain.
    for (int j = 0; j < HID; ++j) {
        float a0 = sb1[j], a1 = 0.f, a2 = 0.f, a3 = 0.f;
        const float4* w1r = (const float4*)(sW1 + j * PCH);
#pragma unroll
        for (int c4 = 0; c4 < PCH / 4; ++c4) {
            float4 w = w1r[c4];
            a0 = fmaf(w.x, p[4 * c4],     a0);
            a1 = fmaf(w.y, p[4 * c4 + 1], a1);
            a2 = fmaf(w.z, p[4 * c4 + 2], a2);
            a3 = fmaf(w.w, p[4 * c4 + 3], a3);
        }
        float hv = fmaxf((a0 + a1) + (a2 + a3), 0.f);
        const float4* w2r = (const float4*)(sW2t + j * CH);
#pragma unroll
        for (int o4 = 0; o4 < CH / 4; ++o4) {
            float4 w = w2r[o4];
            upd[4 * o4]     = fmaf(w.x, hv, upd[4 * o4]);
            upd[4 * o4 + 1] = fmaf(w.y, hv, upd[4 * o4 + 1]);
            upd[4 * o4 + 2] = fmaf(w.z, hv, upd[4 * o4 + 2]);
            upd[4 * o4 + 3] = fmaf(w.w, hv, upd[4 * o4 + 3]);
        }
    }

    const float fire = (ru[(size_t)b * HW * HW + y * HW + xx] <= 0.5f) ? 1.f : 0.f;
    const size_t base = (size_t)b * CH * HW * HW + y * HW + xx;
#pragma unroll
    for (int o = 0; o < CH; ++o) {
        size_t idx = base + (size_t)o * HW * HW;
        g_x2[idx] = x[idx] + upd[o] * fire;
    }
}

// ---------------------------------------------------------------------------
// Kernel 2: life = (maxpool3x3(x[ch3]) > .1) & (maxpool3x3(x2[ch3]) > .1);
//           out = x2 * life. One thread per pixel, loops 32 channels.
// ---------------------------------------------------------------------------
__global__ __launch_bounds__(256)
void nca_mask_kernel(const float* __restrict__ x, float* __restrict__ out)
{
    int gid = blockIdx.x * 256 + threadIdx.x;
    int b  = gid >> 16;
    int y  = (gid >> 8) & 255;
    int xx = gid & 255;

    const float* xc  = x    + ((size_t)b * CH + 3) * HW * HW;
    const float* x2c = g_x2 + ((size_t)b * CH + 3) * HW * HW;

    float m1 = -1e30f, m2 = -1e30f;
    int y0 = y > 0 ? y - 1 : 0, y1 = y < HW - 1 ? y + 1 : HW - 1;
    int x0 = xx > 0 ? xx - 1 : 0, x1 = xx < HW - 1 ? xx + 1 : HW - 1;
    for (int yy = y0; yy <= y1; ++yy)
        for (int xw = x0; xw <= x1; ++xw) {
            m1 = fmaxf(m1, xc[yy * HW + xw]);
            m2 = fmaxf(m2, x2c[yy * HW + xw]);
        }
    float life = (m1 > 0.1f && m2 > 0.1f) ? 1.f : 0.f;

    size_t base = (size_t)b * CH * HW * HW + y * HW + xx;
#pragma unroll
    for (int o = 0; o < CH; ++o)
        out[base + (size_t)o * HW * HW] = g_x2[base + (size_t)o * HW * HW] * life;
}

// ---------------------------------------------------------------------------
extern "C" void kernel_launch(void* const* d_in, const int* in_sizes, int n_in,
                              void* d_out, int out_size)
{
    const float* x  = (const float*)d_in[0];
    const float* ru = (const float*)d_in[1];
    const float* W1 = (const float*)d_in[2];
    const float* b1 = (const float*)d_in[3];
    const float* W2 = (const float*)d_in[4];
    float* out = (float*)d_out;

    const int smem_bytes = (HID * PCH + HID * CH + HID) * (int)sizeof(float);  // 132096
    cudaFuncSetAttribute(nca_update_kernel,
                         cudaFuncAttributeMaxDynamicSharedMemorySize, smem_bytes);

    nca_update_kernel<<<8 * HW, 256, smem_bytes>>>(x, ru, W1, b1, W2);
    nca_mask_kernel<<<(8 * HW * HW) / 256, 256>>>(x, out);
}

// round 4
// speedup vs baseline: 2.2983x; 2.2983x over previous
#include <cuda_runtime.h>
#include <cuda_bf16.h>
#include <cstdint>

#define HW 256
#define CHN 32
#define HID 256
#define K1 96
#define SP 104          // row stride (bf16 elems) for P / W1
#define SH 264          // row stride (bf16 elems) for H / W2
#define TM 64           // pixels per tile
#define NTILES 8192
#define NCTAS 148

// smem byte offsets
#define OFF_W1H 0
#define OFF_W1M (OFF_W1H + HID*SP*2)          // 53248
#define OFF_W2H (OFF_W1M + HID*SP*2)          // 106496
#define OFF_B1  (OFF_W2H + CHN*SH*2)          // 123392
#define OFF_W2R3 (OFF_B1 + HID*4)             // 124416
#define OFF_PH  (OFF_W2R3 + HID*4)            // 125440
#define OFF_PM  (OFF_PH + TM*SP*2)            // 138752
#define OFF_H   (OFF_PM + TM*SP*2)            // 152064
#define OFF_C3  (OFF_H + TM*SH*2)             // 185856
#define OFF_PART OFF_PH                        // 2*64*32*4 = 16384 <= 26624 (dead P region)
#define SMEM_TOTAL (OFF_C3 + TM*4 + 16)       // 186128

__device__ float g_x2[8 * CHN * HW * HW];

__device__ __forceinline__ uint32_t smem_u32(const void* p) {
    uint32_t a;
    asm("{ .reg .u64 t; cvta.to.shared.u64 t, %1; cvt.u32.u64 %0, t; }" : "=r"(a) : "l"(p));
    return a;
}
__device__ __forceinline__ void ldm_x4(uint32_t a, uint32_t& r0, uint32_t& r1, uint32_t& r2, uint32_t& r3) {
    asm volatile("ldmatrix.sync.aligned.m8n8.x4.shared.b16 {%0,%1,%2,%3}, [%4];"
                 : "=r"(r0), "=r"(r1), "=r"(r2), "=r"(r3) : "r"(a));
}
__device__ __forceinline__ void ldm_x2(uint32_t a, uint32_t& r0, uint32_t& r1) {
    asm volatile("ldmatrix.sync.aligned.m8n8.x2.shared.b16 {%0,%1}, [%2];"
                 : "=r"(r0), "=r"(r1) : "r"(a));
}
__device__ __forceinline__ void mma16816(float* d, const uint32_t* a, const uint32_t* b) {
    asm volatile("mma.sync.aligned.m16n8k16.row.col.f32.bf16.bf16.f32 "
                 "{%0,%1,%2,%3}, {%4,%5,%6,%7}, {%8,%9}, {%0,%1,%2,%3};"
                 : "+f"(d[0]), "+f"(d[1]), "+f"(d[2]), "+f"(d[3])
                 : "r"(a[0]), "r"(a[1]), "r"(a[2]), "r"(a[3]), "r"(b[0]), "r"(b[1]));
}
__device__ __forceinline__ uint32_t pack2(float lo, float hi) {
    __nv_bfloat162 t = __floats2bfloat162_rn(lo, hi);
    return *(uint32_t*)&t;
}

// ---------------------------------------------------------------------------
__global__ __launch_bounds__(256, 1)
void nca_mma_kernel(const float* __restrict__ x, const float* __restrict__ ru,
                    const float* __restrict__ W1, const float* __restrict__ b1,
                    const float* __restrict__ W2)
{
    extern __shared__ char smem[];
    const uint32_t sbase = smem_u32(smem);
    const int tid = threadIdx.x;
    const int wid = tid >> 5;
    const int l   = tid & 31;

    // ---- one-time: weights into smem (W1 hi/mid bf16, W2 hi bf16, b1/W2row3 fp32)
    for (int idx = tid; idx < HID * K1; idx += 256) {
        int n = idx / K1, k = idx - n * K1;
        float v = W1[idx];
        __nv_bfloat16 h = __float2bfloat16_rn(v);
        float r = v - __bfloat162float(h);
        *(__nv_bfloat16*)(smem + OFF_W1H + (n * SP + k) * 2) = h;
        *(__nv_bfloat16*)(smem + OFF_W1M + (n * SP + k) * 2) = __float2bfloat16_rn(r);
    }
    for (int idx = tid; idx < CHN * HID; idx += 256) {
        int n = idx >> 8, k = idx & 255;
        *(__nv_bfloat16*)(smem + OFF_W2H + (n * SH + k) * 2) = __float2bfloat16_rn(W2[idx]);
    }
    for (int idx = tid; idx < HID; idx += 256) {
        ((float*)(smem + OFF_B1))[idx]   = b1[idx];
        ((float*)(smem + OFF_W2R3))[idx] = W2[3 * HID + idx];
    }
    if (tid < TM) ((float*)(smem + OFF_C3))[tid] = 0.f;
    __syncthreads();

    const float* b1f   = (const float*)(smem + OFF_B1);
    const float* w2r3  = (const float*)(smem + OFF_W2R3);
    float*       sC3   = (float*)(smem + OFF_C3);
    float*       sPart = (float*)(smem + OFF_PART);

    const int q  = l >> 2;           // accum row-within-m16
    const int cb = 2 * (l & 3);      // accum col pair base

    for (int tile = blockIdx.x; tile < NTILES; tile += NCTAS) {
        const int b  = tile >> 10;
        const int rr = tile & 1023;
        const int y  = rr >> 2;
        const int xb = (rr & 3) << 6;

        // ============ Phase A: perceive + hi/mid split into sP ============
        {
            const int c0 = wid * 4;
            const float* xim = x + (size_t)b * CHN * HW * HW;
            const bool ym = (y > 0), yp = (y < HW - 1);
#pragma unroll
            for (int half = 0; half < 2; ++half) {
                const int pp = l + 32 * half;
                const int px = xb + pp;
                const bool xm = (px > 0), xp = (px < HW - 1);
#pragma unroll
                for (int cc = 0; cc < 4; ++cc) {
                    const int c = c0 + cc;
                    const float* xc = xim + (size_t)c * HW * HW + (size_t)y * HW + px;
                    float c00 = (ym && xm) ? xc[-HW - 1] : 0.f;
                    float c01 =  ym        ? xc[-HW]     : 0.f;
                    float c02 = (ym && xp) ? xc[-HW + 1] : 0.f;
                    float c10 =  xm        ? xc[-1]      : 0.f;
                    float c11 =              xc[0];
                    float c12 =  xp        ? xc[1]       : 0.f;
                    float c20 = (yp && xm) ? xc[HW - 1]  : 0.f;
                    float c21 =  yp        ? xc[HW]      : 0.f;
                    float c22 = (yp && xp) ? xc[HW + 1]  : 0.f;
                    float v0 = c11;
                    float v1 = ((c02 - c00) + 2.f * (c12 - c10) + (c22 - c20)) * 0.125f;
                    float v2 = ((c20 - c00) + 2.f * (c21 - c01) + (c22 - c02)) * 0.125f;
                    const int base = pp * SP + 3 * c;
#pragma unroll
                    for (int j = 0; j < 3; ++j) {
                        float v = (j == 0) ? v0 : (j == 1) ? v1 : v2;
                        __nv_bfloat16 h = __float2bfloat16_rn(v);
                        *(__nv_bfloat16*)(smem + OFF_PH + (base + j) * 2) = h;
                        *(__nv_bfloat16*)(smem + OFF_PM + (base + j) * 2) =
                            __float2bfloat16_rn(v - __bfloat162float(h));
                    }
                }
            }
        }
        __syncthreads();

        // ============ Phase B: GEMM1 (M64 x N256 x K96, 3 products) ============
        const int wm = wid >> 2, wn = wid & 3;     // 2M x 4N
        float acc[2][8][4];
#pragma unroll
        for (int i = 0; i < 2; ++i)
#pragma unroll
            for (int j = 0; j < 8; ++j)
#pragma unroll
                for (int e = 0; e < 4; ++e) acc[i][j][e] = 0.f;

        {
            const uint32_t aTab[3] = {sbase + OFF_PH, sbase + OFF_PH, sbase + OFF_PM};
            const uint32_t bTab[3] = {sbase + OFF_W1H, sbase + OFF_W1M, sbase + OFF_W1H};
#pragma unroll
            for (int prod = 0; prod < 3; ++prod) {
                const uint32_t Ab = aTab[prod], Bb = bTab[prod];
#pragma unroll
                for (int ks = 0; ks < 6; ++ks) {
                    const int k0 = ks * 16;
                    uint32_t af[2][4];
#pragma unroll
                    for (int i = 0; i < 2; ++i) {
                        uint32_t row = wm * 32 + i * 16 + (l & 15);
                        ldm_x4(Ab + (row * SP + k0 + ((l >> 4) << 3)) * 2,
                               af[i][0], af[i][1], af[i][2], af[i][3]);
                    }
                    uint32_t bf[8][2];
#pragma unroll
                    for (int j = 0; j < 8; ++j) {
                        uint32_t rn = wn * 64 + j * 8 + (l & 7);
                        ldm_x2(Bb + (rn * SP + k0 + (((l >> 3) & 1) << 3)) * 2,
                               bf[j][0], bf[j][1]);
                    }
#pragma unroll
                    for (int i = 0; i < 2; ++i)
#pragma unroll
                        for (int j = 0; j < 8; ++j) mma16816(acc[i][j], af[i], bf[j]);
                }
            }
        }

        // ============ Phase C: epilogue1 — bias+relu, pack H, exact ch3 dot ============
        {
            float p3[2][2] = {{0.f, 0.f}, {0.f, 0.f}};
#pragma unroll
            for (int i = 0; i < 2; ++i) {
                const int m0 = wm * 32 + i * 16 + q;
#pragma unroll
                for (int j = 0; j < 8; ++j) {
                    const int n0 = wn * 64 + j * 8 + cb;
                    float h0 = fmaxf(acc[i][j][0] + b1f[n0],     0.f);
                    float h1 = fmaxf(acc[i][j][1] + b1f[n0 + 1], 0.f);
                    float h2 = fmaxf(acc[i][j][2] + b1f[n0],     0.f);
                    float h3 = fmaxf(acc[i][j][3] + b1f[n0 + 1], 0.f);
                    p3[i][0] += h0 * w2r3[n0] + h1 * w2r3[n0 + 1];
                    p3[i][1] += h2 * w2r3[n0] + h3 * w2r3[n0 + 1];
                    *(uint32_t*)(smem + OFF_H + (m0 * SH + n0) * 2)       = pack2(h0, h1);
                    *(uint32_t*)(smem + OFF_H + ((m0 + 8) * SH + n0) * 2) = pack2(h2, h3);
                }
            }
#pragma unroll
            for (int i = 0; i < 2; ++i)
#pragma unroll
                for (int r = 0; r < 2; ++r) {
                    float v = p3[i][r];
                    v += __shfl_xor_sync(0xFFFFFFFF, v, 1);
                    v += __shfl_xor_sync(0xFFFFFFFF, v, 2);
                    if ((l & 3) == 0)
                        atomicAdd(&sC3[wm * 32 + i * 16 + q + r * 8], v);
                }
        }
        __syncthreads();

        // ch3 finalize: exact x2[ch3] -> gmem, then clear sC3 for next tile
        if (tid < TM) {
            const int m = tid, px = xb + m;
            const size_t pix = (size_t)b * HW * HW + (size_t)y * HW + px;
            const float fire = (ru[pix] <= 0.5f) ? 1.f : 0.f;
            const size_t i3 = ((size_t)b * CHN + 3) * HW * HW + (size_t)y * HW + px;
            g_x2[i3] = x[i3] + sC3[m] * fire;
            sC3[m] = 0.f;
        }

        // ============ Phase D: GEMM2 (M64 x N32 x K256, hi only) ============
        {
            const int wm2 = wid & 1, wn2 = (wid >> 1) & 1, wk2 = wid >> 2;
            float ac2[2][2][4];
#pragma unroll
            for (int i = 0; i < 2; ++i)
#pragma unroll
                for (int j = 0; j < 2; ++j)
#pragma unroll
                    for (int e = 0; e < 4; ++e) ac2[i][j][e] = 0.f;
            const uint32_t Hb = sbase + OFF_H, W2b = sbase + OFF_W2H;
#pragma unroll
            for (int ks = 0; ks < 8; ++ks) {
                const int k0 = wk2 * 128 + ks * 16;
                uint32_t af[2][4];
#pragma unroll
                for (int i = 0; i < 2; ++i) {
                    uint32_t row = wm2 * 32 + i * 16 + (l & 15);
                    ldm_x4(Hb + (row * SH + k0 + ((l >> 4) << 3)) * 2,
                           af[i][0], af[i][1], af[i][2], af[i][3]);
                }
                uint32_t bf[2][2];
#pragma unroll
                for (int j = 0; j < 2; ++j) {
                    uint32_t rn = wn2 * 16 + j * 8 + (l & 7);
                    ldm_x2(W2b + (rn * SH + k0 + (((l >> 3) & 1) << 3)) * 2,
                           bf[j][0], bf[j][1]);
                }
#pragma unroll
                for (int i = 0; i < 2; ++i)
#pragma unroll
                    for (int j = 0; j < 2; ++j) mma16816(ac2[i][j], af[i], bf[j]);
            }
            __syncthreads();   // sPart aliases sP: GEMM1 reads & next writes ordered
#pragma unroll
            for (int i = 0; i < 2; ++i)
#pragma unroll
                for (int j = 0; j < 2; ++j)
#pragma unroll
                    for (int e = 0; e < 4; ++e) {
                        const int m = wm2 * 32 + i * 16 + q + (e >> 1) * 8;
                        const int n = wn2 * 16 + j * 8 + cb + (e & 1);
                        sPart[(wk2 * TM + m) * 32 + n] = ac2[i][j][e];
                    }
        }
        __syncthreads();

        // ============ Phase E: writeback (skip ch3) ============
        {
            const int m = tid & 63, ng = tid >> 6;
            const int px = xb + m;
            const size_t pix = (size_t)b * HW * HW + (size_t)y * HW + px;
            const float fire = (ru[pix] <= 0.5f) ? 1.f : 0.f;
#pragma unroll
            for (int q2 = 0; q2 < 8; ++q2) {
                const int ch = ng * 8 + q2;
                if (ch == 3) continue;
                const float upd = sPart[m * 32 + ch] + sPart[(TM + m) * 32 + ch];
                const size_t idx = ((size_t)b * CHN + ch) * HW * HW + (size_t)y * HW + px;
                g_x2[idx] = x[idx] + upd * fire;
            }
        }
        __syncthreads();
    }
}

// ---------------------------------------------------------------------------
__global__ __launch_bounds__(256)
void nca_mask_kernel(const float* __restrict__ x, float* __restrict__ out)
{
    int gid = blockIdx.x * 256 + threadIdx.x;
    int b  = gid >> 16;
    int y  = (gid >> 8) & 255;
    int xx = gid & 255;

    const float* xc  = x    + ((size_t)b * CHN + 3) * HW * HW;
    const float* x2c = g_x2 + ((size_t)b * CHN + 3) * HW * HW;

    float m1 = -1e30f, m2 = -1e30f;
    int y0 = y > 0 ? y - 1 : 0, y1 = y < HW - 1 ? y + 1 : HW - 1;
    int x0 = xx > 0 ? xx - 1 : 0, x1 = xx < HW - 1 ? xx + 1 : HW - 1;
    for (int yy = y0; yy <= y1; ++yy)
        for (int xw = x0; xw <= x1; ++xw) {
            m1 = fmaxf(m1, xc[yy * HW + xw]);
            m2 = fmaxf(m2, x2c[yy * HW + xw]);
        }
    float life = (m1 > 0.1f && m2 > 0.1f) ? 1.f : 0.f;

    size_t base = (size_t)b * CHN * HW * HW + (size_t)y * HW + xx;
#pragma unroll
    for (int o = 0; o < CHN; ++o)
        out[base + (size_t)o * HW * HW] = g_x2[base + (size_t)o * HW * HW] * life;
}

// ---------------------------------------------------------------------------
extern "C" void kernel_launch(void* const* d_in, const int* in_sizes, int n_in,
                              void* d_out, int out_size)
{
    const float* x  = (const float*)d_in[0];
    const float* ru = (const float*)d_in[1];
    const float* W1 = (const float*)d_in[2];
    const float* b1 = (const float*)d_in[3];
    const float* W2 = (const float*)d_in[4];
    float* out = (float*)d_out;

    cudaFuncSetAttribute(nca_mma_kernel,
                         cudaFuncAttributeMaxDynamicSharedMemorySize, SMEM_TOTAL);
    nca_mma_kernel<<<NCTAS, 256, SMEM_TOTAL>>>(x, ru, W1, b1, W2);
    nca_mask_kernel<<<(8 * HW * HW) / 256, 256>>>(x, out);
}

// round 5
// speedup vs baseline: 3.6710x; 1.5972x over previous
#include <cuda_runtime.h>
#include <cuda_bf16.h>
#include <cstdint>

#define HW 256
#define CHN 32
#define HID 256
#define K1 96
#define SP 104          // row stride (bf16 elems) for P / W1
#define SH 264          // row stride (bf16 elems) for H / W2
#define TM 64           // pixels per tile
#define NTILES 8192
#define NCTAS 148

// smem byte offsets
#define OFF_W1H 0
#define OFF_W1M (OFF_W1H + HID*SP*2)          // 53248
#define OFF_W2H (OFF_W1M + HID*SP*2)          // 106496
#define OFF_B1  (OFF_W2H + CHN*SH*2)          // 123392
#define OFF_W2R3 (OFF_B1 + HID*4)             // 124416
#define OFF_PH  (OFF_W2R3 + HID*4)            // 125440
#define OFF_PM  (OFF_PH + TM*SP*2)            // 138752
#define OFF_H   (OFF_PM + TM*SP*2)            // 152064
#define OFF_C3  (OFF_H + TM*SH*2)             // 185856
#define OFF_PART OFF_PH                        // 16384 <= 26624 (dead P region)
#define OFF_RB  (OFF_C3 + TM*4 + 16)          // 186128 (16B aligned)
#define RB_CH   220                            // words per channel: 3*72 + 4 pad (880B)
#define RB_ROW  72                             // words per row (288B)
#define OFF_XC  (OFF_RB + CHN*RB_CH*4)        // 214288
#define SMEM_TOTAL (OFF_XC + TM*33*4)         // 222736

__device__ float g_x2[8 * CHN * HW * HW];

__device__ __forceinline__ uint32_t smem_u32(const void* p) {
    uint32_t a;
    asm("{ .reg .u64 t; cvta.to.shared.u64 t, %1; cvt.u32.u64 %0, t; }" : "=r"(a) : "l"(p));
    return a;
}
__device__ __forceinline__ void ldm_x4(uint32_t a, uint32_t& r0, uint32_t& r1, uint32_t& r2, uint32_t& r3) {
    asm volatile("ldmatrix.sync.aligned.m8n8.x4.shared.b16 {%0,%1,%2,%3}, [%4];"
                 : "=r"(r0), "=r"(r1), "=r"(r2), "=r"(r3) : "r"(a));
}
__device__ __forceinline__ void ldm_x2(uint32_t a, uint32_t& r0, uint32_t& r1) {
    asm volatile("ldmatrix.sync.aligned.m8n8.x2.shared.b16 {%0,%1}, [%2];"
                 : "=r"(r0), "=r"(r1) : "r"(a));
}
__device__ __forceinline__ void mma16816(float* d, const uint32_t* a, const uint32_t* b) {
    asm volatile("mma.sync.aligned.m16n8k16.row.col.f32.bf16.bf16.f32 "
                 "{%0,%1,%2,%3}, {%4,%5,%6,%7}, {%8,%9}, {%0,%1,%2,%3};"
                 : "+f"(d[0]), "+f"(d[1]), "+f"(d[2]), "+f"(d[3])
                 : "r"(a[0]), "r"(a[1]), "r"(a[2]), "r"(a[3]), "r"(b[0]), "r"(b[1]));
}
__device__ __forceinline__ uint32_t pack2(float lo, float hi) {
    __nv_bfloat162 t = __floats2bfloat162_rn(lo, hi);
    return *(uint32_t*)&t;
}

// Prefetch one tile's input rows (3 rows x 72 px x 32 ch) into RB via cp.async.
// OOB chunks (y edges, x edges) are zero-filled via src-size=0.
__device__ __forceinline__ void prefetch_tile(uint32_t rb_base, const float* __restrict__ x,
                                              int tile, int tid)
{
    const int b  = tile >> 10;
    const int rr = tile & 1023;
    const int y  = rr >> 2;
    const int xb = (rr & 3) << 6;
    const float* xim = x + (uint32_t)b * (CHN * HW * HW);
    // 32 ch * 3 rows * 18 chunks(16B) = 1728 chunks
    for (int i = tid; i < 1728; i += 256) {
        const int ch  = i / 54;
        const int rem = i - ch * 54;
        const int row = rem / 18;
        const int cx  = rem - row * 18;
        const int srow = y - 1 + row;
        const int px0  = xb - 4 + cx * 4;
        const bool ok = (srow >= 0) & (srow < HW) & (px0 >= 0) & (px0 <= HW - 4);
        const float* src = xim + ((uint32_t)ch << 16) + ((uint32_t)(srow & 255) << 8) + (px0 & 255);
        const uint32_t dst = rb_base + (uint32_t)(ch * RB_CH + row * RB_ROW + cx * 4) * 4;
        const int sz = ok ? 16 : 0;
        asm volatile("cp.async.ca.shared.global [%0], [%1], 16, %2;"
                     :: "r"(dst), "l"(src), "r"(sz));
    }
    asm volatile("cp.async.commit_group;" ::: "memory");
}

// ---------------------------------------------------------------------------
__global__ __launch_bounds__(256, 1)
void nca_mma_kernel(const float* __restrict__ x, const float* __restrict__ ru,
                    const float* __restrict__ W1, const float* __restrict__ b1,
                    const float* __restrict__ W2)
{
    extern __shared__ char smem[];
    const uint32_t sbase = smem_u32(smem);
    const int tid = threadIdx.x;
    const int wid = tid >> 5;
    const int l   = tid & 31;

    // ---- one-time: weights into smem (W1 hi/mid bf16, W2 hi bf16, b1/W2row3 fp32)
    for (int idx = tid; idx < HID * K1; idx += 256) {
        int n = idx / K1, k = idx - n * K1;
        float v = W1[idx];
        __nv_bfloat16 h = __float2bfloat16_rn(v);
        float r = v - __bfloat162float(h);
        *(__nv_bfloat16*)(smem + OFF_W1H + (n * SP + k) * 2) = h;
        *(__nv_bfloat16*)(smem + OFF_W1M + (n * SP + k) * 2) = __float2bfloat16_rn(r);
    }
    for (int idx = tid; idx < CHN * HID; idx += 256) {
        int n = idx >> 8, k = idx & 255;
        *(__nv_bfloat16*)(smem + OFF_W2H + (n * SH + k) * 2) = __float2bfloat16_rn(W2[idx]);
    }
    for (int idx = tid; idx < HID; idx += 256) {
        ((float*)(smem + OFF_B1))[idx]   = b1[idx];
        ((float*)(smem + OFF_W2R3))[idx] = W2[3 * HID + idx];
    }
    if (tid < TM) ((float*)(smem + OFF_C3))[tid] = 0.f;
    __syncthreads();

    const float* b1f   = (const float*)(smem + OFF_B1);
    const float* w2r3  = (const float*)(smem + OFF_W2R3);
    float*       sC3   = (float*)(smem + OFF_C3);
    float*       sPart = (float*)(smem + OFF_PART);
    const float* rb    = (const float*)(smem + OFF_RB);
    float*       sXC   = (float*)(smem + OFF_XC);

    const int q  = l >> 2;
    const int cb = 2 * (l & 3);

    // prologue prefetch for first tile
    if (blockIdx.x < NTILES) prefetch_tile(sbase + OFF_RB, x, blockIdx.x, tid);

    for (int tile = blockIdx.x; tile < NTILES; tile += NCTAS) {
        const int b  = tile >> 10;
        const int rr = tile & 1023;
        const int y  = rr >> 2;
        const int xb = (rr & 3) << 6;

        asm volatile("cp.async.wait_group 0;" ::: "memory");
        __syncthreads();

        // ============ Phase A: perceive from RB + hi/mid split into sP ============
        {
            const int c0 = wid * 4;
#pragma unroll
            for (int half = 0; half < 2; ++half) {
                const int pp = l + 32 * half;
#pragma unroll
                for (int cc = 0; cc < 4; ++cc) {
                    const int c = c0 + cc;
                    const float* r0 = rb + c * RB_CH + (pp + 3);
                    const float* r1 = r0 + RB_ROW;
                    const float* r2 = r1 + RB_ROW;
                    float a00 = r0[0], a01 = r0[1], a02 = r0[2];
                    float a10 = r1[0], a11 = r1[1], a12 = r1[2];
                    float a20 = r2[0], a21 = r2[1], a22 = r2[2];
                    float v0 = a11;
                    float v1 = ((a02 - a00) + 2.f * (a12 - a10) + (a22 - a20)) * 0.125f;
                    float v2 = ((a20 - a00) + 2.f * (a21 - a01) + (a22 - a02)) * 0.125f;
                    sXC[pp * 33 + c] = v0;
                    const int base = pp * SP + 3 * c;
#pragma unroll
                    for (int j = 0; j < 3; ++j) {
                        float v = (j == 0) ? v0 : (j == 1) ? v1 : v2;
                        __nv_bfloat16 h = __float2bfloat16_rn(v);
                        *(__nv_bfloat16*)(smem + OFF_PH + (base + j) * 2) = h;
                        *(__nv_bfloat16*)(smem + OFF_PM + (base + j) * 2) =
                            __float2bfloat16_rn(v - __bfloat162float(h));
                    }
                }
            }
        }
        __syncthreads();

        // issue prefetch for next tile (RB free now; overlaps GEMMs)
        if (tile + NCTAS < NTILES) prefetch_tile(sbase + OFF_RB, x, tile + NCTAS, tid);

        // ============ Phase B: GEMM1 (M64 x N256 x K96, 3 products) ============
        const int wm = wid >> 2, wn = wid & 3;
        float acc[2][8][4];
#pragma unroll
        for (int i = 0; i < 2; ++i)
#pragma unroll
            for (int j = 0; j < 8; ++j)
#pragma unroll
                for (int e = 0; e < 4; ++e) acc[i][j][e] = 0.f;
        {
            const uint32_t aTab[3] = {sbase + OFF_PH, sbase + OFF_PH, sbase + OFF_PM};
            const uint32_t bTab[3] = {sbase + OFF_W1H, sbase + OFF_W1M, sbase + OFF_W1H};
#pragma unroll
            for (int prod = 0; prod < 3; ++prod) {
                const uint32_t Ab = aTab[prod], Bb = bTab[prod];
#pragma unroll
                for (int ks = 0; ks < 6; ++ks) {
                    const int k0 = ks * 16;
                    uint32_t af[2][4];
#pragma unroll
                    for (int i = 0; i < 2; ++i) {
                        uint32_t row = wm * 32 + i * 16 + (l & 15);
                        ldm_x4(Ab + (row * SP + k0 + ((l >> 4) << 3)) * 2,
                               af[i][0], af[i][1], af[i][2], af[i][3]);
                    }
                    uint32_t bf[8][2];
#pragma unroll
                    for (int j = 0; j < 8; ++j) {
                        uint32_t rn = wn * 64 + j * 8 + (l & 7);
                        ldm_x2(Bb + (rn * SP + k0 + (((l >> 3) & 1) << 3)) * 2,
                               bf[j][0], bf[j][1]);
                    }
#pragma unroll
                    for (int i = 0; i < 2; ++i)
#pragma unroll
                        for (int j = 0; j < 8; ++j) mma16816(acc[i][j], af[i], bf[j]);
                }
            }
        }

        // ============ Phase C: epilogue1 — bias+relu, pack H, exact ch3 dot ============
        {
            float p3[2][2] = {{0.f, 0.f}, {0.f, 0.f}};
#pragma unroll
            for (int i = 0; i < 2; ++i) {
                const int m0 = wm * 32 + i * 16 + q;
#pragma unroll
                for (int j = 0; j < 8; ++j) {
                    const int n0 = wn * 64 + j * 8 + cb;
                    float h0 = fmaxf(acc[i][j][0] + b1f[n0],     0.f);
                    float h1 = fmaxf(acc[i][j][1] + b1f[n0 + 1], 0.f);
                    float h2 = fmaxf(acc[i][j][2] + b1f[n0],     0.f);
                    float h3 = fmaxf(acc[i][j][3] + b1f[n0 + 1], 0.f);
                    p3[i][0] += h0 * w2r3[n0] + h1 * w2r3[n0 + 1];
                    p3[i][1] += h2 * w2r3[n0] + h3 * w2r3[n0 + 1];
                    *(uint32_t*)(smem + OFF_H + (m0 * SH + n0) * 2)       = pack2(h0, h1);
                    *(uint32_t*)(smem + OFF_H + ((m0 + 8) * SH + n0) * 2) = pack2(h2, h3);
                }
            }
#pragma unroll
            for (int i = 0; i < 2; ++i)
#pragma unroll
                for (int r = 0; r < 2; ++r) {
                    float v = p3[i][r];
                    v += __shfl_xor_sync(0xFFFFFFFF, v, 1);
                    v += __shfl_xor_sync(0xFFFFFFFF, v, 2);
                    if ((l & 3) == 0)
                        atomicAdd(&sC3[wm * 32 + i * 16 + q + r * 8], v);
                }
        }
        __syncthreads();

        // ch3 finalize: exact x2[ch3] from sXC, then clear sC3
        if (tid < TM) {
            const int m = tid, px = xb + m;
            const uint32_t pix = ((uint32_t)b << 16) + ((uint32_t)y << 8) + px;
            const float fire = (ru[pix] <= 0.5f) ? 1.f : 0.f;
            const uint32_t i3 = (((uint32_t)b * CHN + 3) << 16) + ((uint32_t)y << 8) + px;
            g_x2[i3] = sXC[m * 33 + 3] + sC3[m] * fire;
            sC3[m] = 0.f;
        }

        // ============ Phase D: GEMM2 (M64 x N32 x K256, hi only) ============
        {
            const int wm2 = wid & 1, wn2 = (wid >> 1) & 1, wk2 = wid >> 2;
            float ac2[2][2][4];
#pragma unroll
            for (int i = 0; i < 2; ++i)
#pragma unroll
                for (int j = 0; j < 2; ++j)
#pragma unroll
                    for (int e = 0; e < 4; ++e) ac2[i][j][e] = 0.f;
            const uint32_t Hb = sbase + OFF_H, W2b = sbase + OFF_W2H;
#pragma unroll
            for (int ks = 0; ks < 8; ++ks) {
                const int k0 = wk2 * 128 + ks * 16;
                uint32_t af[2][4];
#pragma unroll
                for (int i = 0; i < 2; ++i) {
                    uint32_t row = wm2 * 32 + i * 16 + (l & 15);
                    ldm_x4(Hb + (row * SH + k0 + ((l >> 4) << 3)) * 2,
                           af[i][0], af[i][1], af[i][2], af[i][3]);
                }
                uint32_t bf[2][2];
#pragma unroll
                for (int j = 0; j < 2; ++j) {
                    uint32_t rn = wn2 * 16 + j * 8 + (l & 7);
                    ldm_x2(W2b + (rn * SH + k0 + (((l >> 3) & 1) << 3)) * 2,
                           bf[j][0], bf[j][1]);
                }
#pragma unroll
                for (int i = 0; i < 2; ++i)
#pragma unroll
                    for (int j = 0; j < 2; ++j) mma16816(ac2[i][j], af[i], bf[j]);
            }
            __syncthreads();   // sPart aliases sP region
#pragma unroll
            for (int i = 0; i < 2; ++i)
#pragma unroll
                for (int j = 0; j < 2; ++j)
#pragma unroll
                    for (int e = 0; e < 4; ++e) {
                        const int m = wm2 * 32 + i * 16 + q + (e >> 1) * 8;
                        const int n = wn2 * 16 + j * 8 + cb + (e & 1);
                        sPart[(wk2 * TM + m) * 32 + n] = ac2[i][j][e];
                    }
        }
        __syncthreads();

        // ============ Phase E: writeback from sXC (skip ch3) ============
        {
            const int m = tid & 63, ng = tid >> 6;
            const int px = xb + m;
            const uint32_t pix = ((uint32_t)b << 16) + ((uint32_t)y << 8) + px;
            const float fire = (ru[pix] <= 0.5f) ? 1.f : 0.f;
#pragma unroll
            for (int q2 = 0; q2 < 8; ++q2) {
                const int ch = ng * 8 + q2;
                if (ch == 3) continue;
                const float upd = sPart[m * 32 + ch] + sPart[(TM + m) * 32 + ch];
                const uint32_t idx = (((uint32_t)b * CHN + ch) << 16) + ((uint32_t)y << 8) + px;
                g_x2[idx] = sXC[m * 33 + ch] + upd * fire;
            }
        }
        __syncthreads();
    }
}

// ---------------------------------------------------------------------------
__global__ __launch_bounds__(256)
void nca_mask_kernel(const float* __restrict__ x, float* __restrict__ out)
{
    int gid = blockIdx.x * 256 + threadIdx.x;
    int b  = gid >> 16;
    int y  = (gid >> 8) & 255;
    int xx = gid & 255;

    const float* xc  = x    + (((uint32_t)b * CHN + 3) << 16);
    const float* x2c = g_x2 + (((uint32_t)b * CHN + 3) << 16);

    float m1 = -1e30f, m2 = -1e30f;
    int y0 = y > 0 ? y - 1 : 0, y1 = y < HW - 1 ? y + 1 : HW - 1;
    int x0 = xx > 0 ? xx - 1 : 0, x1 = xx < HW - 1 ? xx + 1 : HW - 1;
    for (int yy = y0; yy <= y1; ++yy)
        for (int xw = x0; xw <= x1; ++xw) {
            m1 = fmaxf(m1, xc[yy * HW + xw]);
            m2 = fmaxf(m2, x2c[yy * HW + xw]);
        }
    float life = (m1 > 0.1f && m2 > 0.1f) ? 1.f : 0.f;

    uint32_t base = ((uint32_t)b * CHN << 16) + ((uint32_t)y << 8) + xx;
#pragma unroll
    for (int o = 0; o < CHN; ++o)
        out[base + ((uint32_t)o << 16)] = g_x2[base + ((uint32_t)o << 16)] * life;
}

// ---------------------------------------------------------------------------
extern "C" void kernel_launch(void* const* d_in, const int* in_sizes, int n_in,
                              void* d_out, int out_size)
{
    const float* x  = (const float*)d_in[0];
    const float* ru = (const float*)d_in[1];
    const float* W1 = (const float*)d_in[2];
    const float* b1 = (const float*)d_in[3];
    const float* W2 = (const float*)d_in[4];
    float* out = (float*)d_out;

    cudaFuncSetAttribute(nca_mma_kernel,
                         cudaFuncAttributeMaxDynamicSharedMemorySize, SMEM_TOTAL);
    nca_mma_kernel<<<NCTAS, 256, SMEM_TOTAL>>>(x, ru, W1, b1, W2);
    nca_mask_kernel<<<(8 * HW * HW) / 256, 256>>>(x, out);
}